// round 3
// baseline (speedup 1.0000x reference)
#include <cuda_runtime.h>
#include <cuda_bf16.h>
#include <math.h>

#define T_TOK 2048
#define HID   1024
#define NEXP  64
#define TOPK  8
#define ISZ   512
#define GRP   128

#define N1 (NEXP*ISZ)   /* 32768, W1 dense cols */
#define N2 (NEXP*HID)   /* 65536, W2 dense cols */

// ---------------- scratch (device globals: no allocation allowed) ----------------
__device__ float g_W1[(size_t)HID * N1];   // 1024 x 32768 dense fp32 (128 MB)
__device__ float g_W2[(size_t)ISZ * N2];   // 512  x 65536 dense fp32 (128 MB)
__device__ int   g_topk_idx[T_TOK*TOPK];
__device__ float g_topk_w[T_TOK*TOPK];
__device__ int   g_cnt[NEXP];
__device__ int   g_base[NEXP];
__device__ int   g_pos[NEXP];
__device__ int   g_tok[T_TOK*TOPK];
__device__ float g_tw[T_TOK*TOPK];

// ---------------- packed f32x2 helpers (full-rate fp32 FMA on sm_103a) ----------
__device__ __forceinline__ void ffma2(unsigned long long &d, unsigned long long a,
                                      unsigned long long b) {
    asm("fma.rn.f32x2 %0, %1, %2, %0;" : "+l"(d) : "l"(a), "l"(b));
}
__device__ __forceinline__ unsigned long long dup2(float f) {
    unsigned long long r; unsigned u = __float_as_uint(f);
    asm("mov.b64 %0, {%1, %1};" : "=l"(r) : "r"(u));
    return r;
}
__device__ __forceinline__ float2 unpk(unsigned long long v) {
    unsigned lo, hi;
    asm("mov.b64 {%0, %1}, %2;" : "=r"(lo), "=r"(hi) : "l"(v));
    return make_float2(__uint_as_float(lo), __uint_as_float(hi));
}

// ---------------- AWQ dequant: qw (K, N/8) int32 -> dense (K, N) fp32 ------------
// nibble j of word -> column c*8+j, shift = (j>>1)*4 + (j&1)*16
__global__ __launch_bounds__(256) void dequant1_kernel(
    const int* __restrict__ qw, const int* __restrict__ qz, const float* __restrict__ sc) {
    int w = blockIdx.x * 256 + threadIdx.x;         // over 1024*4096 words
    int k = w >> 12;
    int c = w & 4095;
    unsigned q  = (unsigned)qw[w];
    unsigned zw = (unsigned)qz[(k >> 7) * 4096 + c];
    const float* srow = sc + (size_t)(k >> 7) * N1 + (size_t)c * 8;
    float* orow = g_W1 + (size_t)k * N1 + (size_t)c * 8;
    float v[8];
#pragma unroll
    for (int j = 0; j < 8; j++) {
        int sh = ((j >> 1) << 2) + ((j & 1) << 4);
        v[j] = ((float)((q >> sh) & 0xFu) - (float)((zw >> sh) & 0xFu)) * srow[j];
    }
    ((float4*)orow)[0] = make_float4(v[0], v[1], v[2], v[3]);
    ((float4*)orow)[1] = make_float4(v[4], v[5], v[6], v[7]);
}

__global__ __launch_bounds__(256) void dequant2_kernel(
    const int* __restrict__ qw, const int* __restrict__ qz, const float* __restrict__ sc) {
    int w = blockIdx.x * 256 + threadIdx.x;         // over 512*8192 words
    int k = w >> 13;
    int c = w & 8191;
    unsigned q  = (unsigned)qw[w];
    unsigned zw = (unsigned)qz[(k >> 7) * 8192 + c];
    const float* srow = sc + (size_t)(k >> 7) * N2 + (size_t)c * 8;
    float* orow = g_W2 + (size_t)k * N2 + (size_t)c * 8;
    float v[8];
#pragma unroll
    for (int j = 0; j < 8; j++) {
        int sh = ((j >> 1) << 2) + ((j & 1) << 4);
        v[j] = ((float)((q >> sh) & 0xFu) - (float)((zw >> sh) & 0xFu)) * srow[j];
    }
    ((float4*)orow)[0] = make_float4(v[0], v[1], v[2], v[3]);
    ((float4*)orow)[1] = make_float4(v[4], v[5], v[6], v[7]);
}

// ---------------- zero out + counters --------------------------------------------
__global__ __launch_bounds__(256) void zero_kernel(float* __restrict__ out) {
    int i = blockIdx.x * 256 + threadIdx.x;
    if (i < T_TOK * HID) out[i] = 0.f;
    if (i < NEXP) { g_cnt[i] = 0; g_pos[i] = 0; }
}

// ---------------- router: logits -> top8 -> renormalized softmax weights ---------
// 4 tokens per block; 256 threads = 64 experts x 4 k-partitions (interleaved k).
__global__ __launch_bounds__(256) void router_kernel(
    const float* __restrict__ x, const float* __restrict__ gw) {
    int tbase = blockIdx.x * 4;
    __shared__ float xs[4][1024];
    __shared__ float part[4][64][4];
    __shared__ float logits[4][64];
    int tid = threadIdx.x;
    for (int i = tid; i < 4096; i += 256) {
        int tt = i >> 10;
        xs[tt][i & 1023] = x[(size_t)(tbase + tt) * HID + (i & 1023)];
    }
    __syncthreads();
    int e = tid >> 2, p = tid & 3;
    const float* wr = gw + (size_t)e * HID;
    float s0 = 0, s1 = 0, s2 = 0, s3 = 0;
    for (int k = 0; k < 256; k++) {
        int idx = k * 4 + p;
        float w = wr[idx];
        s0 += xs[0][idx] * w; s1 += xs[1][idx] * w;
        s2 += xs[2][idx] * w; s3 += xs[3][idx] * w;
    }
    part[0][e][p] = s0; part[1][e][p] = s1; part[2][e][p] = s2; part[3][e][p] = s3;
    __syncthreads();
    {   // reduce 4 partials per (token, expert)
        int tt = tid >> 6, ee = tid & 63;
        logits[tt][ee] = part[tt][ee][0] + part[tt][ee][1] + part[tt][ee][2] + part[tt][ee][3];
    }
    __syncthreads();
    if (tid < 4) {
        int t = tbase + tid;
        unsigned long long used = 0ull;
        int idx[8]; float lv[8];
        for (int r = 0; r < 8; r++) {           // top-8, lowest index wins ties
            float best = -1e30f; int bi = 0;
            for (int i = 0; i < 64; i++) {
                if (!((used >> i) & 1ull) && logits[tid][i] > best) { best = logits[tid][i]; bi = i; }
            }
            used |= 1ull << bi; idx[r] = bi; lv[r] = best;
        }
        // softmax over chosen set == softmax-all then renormalize over top-k
        float m = lv[0], sum = 0.f, wk[8];
        for (int r = 0; r < 8; r++) { wk[r] = expf(lv[r] - m); sum += wk[r]; }
        float inv = 1.f / sum;
        for (int r = 0; r < 8; r++) {
            g_topk_idx[t * TOPK + r] = idx[r];
            g_topk_w[t * TOPK + r]   = wk[r] * inv;
            atomicAdd(&g_cnt[idx[r]], 1);
        }
    }
}

// ---------------- scan + scatter into per-expert buckets -------------------------
__global__ void scan_kernel() {
    int acc = 0;
    for (int i = 0; i < NEXP; i++) { g_base[i] = acc; acc += g_cnt[i]; }
}

__global__ __launch_bounds__(256) void scatter_kernel() {
    int p = blockIdx.x * 256 + threadIdx.x;     // over T*TOPK
    if (p >= T_TOK * TOPK) return;
    int e = g_topk_idx[p];
    int pos = g_base[e] + atomicAdd(&g_pos[e], 1);
    g_tok[pos] = p >> 3;
    g_tw[pos]  = g_topk_w[p];
}

// ---------------- fused expert FFN -----------------------------------------------
// block = (expert e, 32-token tile). Phase1: Hs = silu(X @ W1e^T) * tw in smem.
// Phase2: out += Hs @ W2e^T via atomicAdd. Microtile 8tok x 8col per thread, f32x2.
#define TB 32
#define KC 32
#define HS_STRIDE 520  /* 512 + 8 pad to break bank conflicts */
#define SMEM_FLOATS (KC*TB + KC*512 + TB*HS_STRIDE + 2*TB)

__global__ __launch_bounds__(256, 1) void ffn_kernel(
    const float* __restrict__ x, float* __restrict__ out) {
    int e = blockIdx.x;
    int cnt = g_cnt[e];
    int tile0 = blockIdx.y * TB;
    if (tile0 >= cnt) return;
    int nt = min(TB, cnt - tile0);
    int base = g_base[e] + tile0;

    extern __shared__ float sm[];
    float* Xs = sm;                          // [KC][TB] transposed x chunk
    float* Ws = Xs + KC * TB;                // [KC][512] weight chunk
    float* Hs = Ws + KC * 512;               // [TB][HS_STRIDE]
    int*   tok_s = (int*)(Hs + TB * HS_STRIDE);
    float* tw_s  = (float*)(tok_s + TB);

    int tid = threadIdx.x;
    if (tid < TB) {
        if (tid < nt) { tok_s[tid] = g_tok[base + tid]; tw_s[tid] = g_tw[base + tid]; }
        else          { tok_s[tid] = 0;                 tw_s[tid] = 0.f; }
    }
    __syncthreads();

    int tc = tid & 63, tr = tid >> 6;
    int i0 = tc * 8, t0 = tr * 8;
    int xt = tid >> 3;            // Xs loader: token
    int xk = (tid & 7) * 4;       // Xs loader: k offset (float4)

    unsigned long long acc[8][4];
#pragma unroll
    for (int v = 0; v < 8; v++)
#pragma unroll
        for (int u = 0; u < 4; u++) acc[v][u] = 0ull;

    // ---- phase 1: h = X @ W1e^T ----
    for (int k0 = 0; k0 < HID; k0 += KC) {
        __syncthreads();
        {
            float4 xv = make_float4(0.f, 0.f, 0.f, 0.f);
            if (xt < nt) xv = *(const float4*)(x + (size_t)tok_s[xt] * HID + k0 + xk);
            Xs[(xk + 0) * TB + xt] = xv.x;
            Xs[(xk + 1) * TB + xt] = xv.y;
            Xs[(xk + 2) * TB + xt] = xv.z;
            Xs[(xk + 3) * TB + xt] = xv.w;
        }
        {
            const float* src = g_W1 + (size_t)k0 * N1 + (size_t)e * ISZ;
#pragma unroll
            for (int r = 0; r < 16; r++) {
                int idx = tid + r * 256;
                int row = idx >> 7, c4 = idx & 127;
                *(float4*)(Ws + row * 512 + c4 * 4) =
                    *(const float4*)(src + (size_t)row * N1 + c4 * 4);
            }
        }
        __syncthreads();
#pragma unroll 4
        for (int kk = 0; kk < KC; kk++) {
            const ulonglong2* wp = (const ulonglong2*)(Ws + kk * 512 + i0);
            ulonglong2 wA = wp[0], wB = wp[1];
            const float* xr = Xs + kk * TB + t0;
#pragma unroll
            for (int v = 0; v < 8; v++) {
                unsigned long long xp = dup2(xr[v]);
                ffma2(acc[v][0], xp, wA.x);
                ffma2(acc[v][1], xp, wA.y);
                ffma2(acc[v][2], xp, wB.x);
                ffma2(acc[v][3], xp, wB.y);
            }
        }
    }

    // silu + combine weight -> Hs[tok][i]
#pragma unroll
    for (int v = 0; v < 8; v++) {
        float tw = tw_s[t0 + v];
        float* hr = Hs + (t0 + v) * HS_STRIDE + i0;
#pragma unroll
        for (int u = 0; u < 4; u++) {
            float2 f = unpk(acc[v][u]);
            hr[u * 2 + 0] = f.x / (1.f + expf(-f.x)) * tw;
            hr[u * 2 + 1] = f.y / (1.f + expf(-f.y)) * tw;
        }
    }

    // ---- phase 2: out += Hs @ W2e^T (two 512-wide output chunks) ----
    for (int n0 = 0; n0 < HID; n0 += 512) {
#pragma unroll
        for (int v = 0; v < 8; v++)
#pragma unroll
            for (int u = 0; u < 4; u++) acc[v][u] = 0ull;

        for (int k0 = 0; k0 < ISZ; k0 += KC) {
            __syncthreads();   // also orders Hs writes before first reads
            const float* src = g_W2 + (size_t)k0 * N2 + (size_t)e * HID + n0;
#pragma unroll
            for (int r = 0; r < 16; r++) {
                int idx = tid + r * 256;
                int row = idx >> 7, c4 = idx & 127;
                *(float4*)(Ws + row * 512 + c4 * 4) =
                    *(const float4*)(src + (size_t)row * N2 + c4 * 4);
            }
            __syncthreads();
#pragma unroll 4
            for (int kk = 0; kk < KC; kk++) {
                const ulonglong2* wp = (const ulonglong2*)(Ws + kk * 512 + i0);
                ulonglong2 wA = wp[0], wB = wp[1];
#pragma unroll
                for (int v = 0; v < 8; v++) {
                    unsigned long long xp = dup2(Hs[(t0 + v) * HS_STRIDE + k0 + kk]);
                    ffma2(acc[v][0], xp, wA.x);
                    ffma2(acc[v][1], xp, wA.y);
                    ffma2(acc[v][2], xp, wB.x);
                    ffma2(acc[v][3], xp, wB.y);
                }
            }
        }
#pragma unroll
        for (int v = 0; v < 8; v++) {
            if (t0 + v < nt) {
                float* op = out + (size_t)tok_s[t0 + v] * HID + n0 + i0;
#pragma unroll
                for (int u = 0; u < 4; u++) {
                    float2 f = unpk(acc[v][u]);
                    atomicAdd(op + u * 2 + 0, f.x);
                    atomicAdd(op + u * 2 + 1, f.y);
                }
            }
        }
    }
}

// ---------------- launch ----------------------------------------------------------
extern "C" void kernel_launch(void* const* d_in, const int* in_sizes, int n_in,
                              void* d_out, int out_size) {
    const float* x   = (const float*)d_in[0];
    const float* gw  = (const float*)d_in[1];
    const int*   qw1 = (const int*)d_in[2];
    const int*   qz1 = (const int*)d_in[3];
    const float* sc1 = (const float*)d_in[4];
    const int*   qw2 = (const int*)d_in[5];
    const int*   qz2 = (const int*)d_in[6];
    const float* sc2 = (const float*)d_in[7];
    float* out = (float*)d_out;

    cudaFuncSetAttribute(ffn_kernel, cudaFuncAttributeMaxDynamicSharedMemorySize,
                         SMEM_FLOATS * 4);

    dequant1_kernel<<<16384, 256>>>(qw1, qz1, sc1);
    dequant2_kernel<<<16384, 256>>>(qw2, qz2, sc2);
    zero_kernel<<<(T_TOK * HID + 255) / 256, 256>>>(out);
    router_kernel<<<T_TOK / 4, 256>>>(x, gw);
    scan_kernel<<<1, 1>>>();
    scatter_kernel<<<(T_TOK * TOPK + 255) / 256, 256>>>();
    ffn_kernel<<<dim3(NEXP, T_TOK / TB), 256, SMEM_FLOATS * 4>>>(x, out);
}

// round 5
// speedup vs baseline: 1.5978x; 1.5978x over previous
#include <cuda_runtime.h>
#include <cuda_bf16.h>
#include <math.h>
#include <stdint.h>

#define T_TOK 2048
#define HID   1024
#define NEXP  64
#define TOPK  8
#define ISZ   512
#define GRP   128

// ================= helpers ========================================================
__device__ __forceinline__ uint32_t smem_to_u32(const void* p) {
    uint32_t a;
    asm("{ .reg .u64 t; cvta.to.shared.u64 t, %1; cvt.u32.u64 %0, t; }" : "=r"(a) : "l"(p));
    return a;
}
#define SW128(o) ((o) ^ (((o) >> 3) & 0x70))

#define CP16(dst, src) \
    asm volatile("cp.async.cg.shared.global [%0], [%1], 16;" \
                 :: "r"((uint32_t)(dst)), "l"((const void*)(src)) : "memory")
#define CP_COMMIT() asm volatile("cp.async.commit_group;" ::: "memory")
#define CP_WAIT0()  asm volatile("cp.async.wait_group 0;" ::: "memory")

__device__ __forceinline__ void ldsm4(uint32_t addr, uint32_t& r0, uint32_t& r1,
                                      uint32_t& r2, uint32_t& r3) {
    asm volatile("ldmatrix.sync.aligned.m8n8.x4.shared.b16 {%0,%1,%2,%3}, [%4];"
                 : "=r"(r0), "=r"(r1), "=r"(r2), "=r"(r3) : "r"(addr));
}
__device__ __forceinline__ void mma16816(float* c, const uint32_t* a,
                                         uint32_t b0, uint32_t b1) {
    asm volatile("mma.sync.aligned.m16n8k16.row.col.f32.bf16.bf16.f32 "
                 "{%0,%1,%2,%3}, {%4,%5,%6,%7}, {%8,%9}, {%0,%1,%2,%3};"
                 : "+f"(c[0]), "+f"(c[1]), "+f"(c[2]), "+f"(c[3])
                 : "r"(a[0]), "r"(a[1]), "r"(a[2]), "r"(a[3]), "r"(b0), "r"(b1));
}
// ldsm address: tile rows of 64 bf16 (128 B), SW128-swizzled, base 1024-aligned.
__device__ __forceinline__ uint32_t ldsm_addr(uint32_t tile_base, int R, int kk, int lane) {
    int g = lane >> 3;
    int row = R + ((g & 1) << 3) + (lane & 7);
    uint32_t off = (uint32_t)(row * 128 + kk * 32 + ((g >> 1) << 4));
    return tile_base + SW128(off);
}

__device__ __forceinline__ void bf16_split(float v, __nv_bfloat16& h, __nv_bfloat16& l) {
    h = __float2bfloat16(v);
    l = __float2bfloat16(v - __bfloat162float(h));
}
__device__ __forceinline__ uint32_t pack2(__nv_bfloat16 a, __nv_bfloat16 b) {
    return (uint32_t)__bfloat16_as_ushort(a) | ((uint32_t)__bfloat16_as_ushort(b) << 16);
}

// ================= device scratch =================================================
__device__ __nv_bfloat16 g_W1h[33554432];  // [E*I=32768][K=1024] (k-major)
__device__ __nv_bfloat16 g_W1l[33554432];
__device__ __nv_bfloat16 g_W2h[33554432];  // [E*H=65536][K=512]
__device__ __nv_bfloat16 g_W2l[33554432];
__device__ __nv_bfloat16 g_Xh[2097152];    // [T=2048][1024]
__device__ __nv_bfloat16 g_Xl[2097152];
__device__ __nv_bfloat16 g_Hh[8388608];    // [16384 slots][512]
__device__ __nv_bfloat16 g_Hl[8388608];
__device__ float         g_O2[16777216];   // [16384 slots][1024]
__device__ int   g_topk_idx[T_TOK*TOPK];
__device__ float g_topk_w[T_TOK*TOPK];
__device__ int   g_cnt[NEXP];
__device__ int   g_base[NEXP];
__device__ int   g_pos[NEXP];
__device__ int   g_tok[T_TOK*TOPK];
__device__ float g_tw[T_TOK*TOPK];
__device__ int   g_slot[T_TOK*TOPK];
__device__ int   g_tile_e[256];
__device__ int   g_tile_off[256];
__device__ int   g_ntiles;

// ================= dequant + split + transpose ===================================
// AWQ nibble j shift = (j>>1)*4 + (j&1)*16; dense column n = c*8+j -> output row n.
#define DQ_S 260
__global__ __launch_bounds__(256) void dequant1_t(
    const int* __restrict__ qw, const int* __restrict__ qz, const float* __restrict__ sc) {
    int c0 = blockIdx.x * 8;       // word columns (of 4096)
    int k0 = blockIdx.y * 256;     // k tile (of 1024)
    extern __shared__ char smraw[];
    __nv_bfloat16* shh = (__nv_bfloat16*)smraw;
    __nv_bfloat16* shl = shh + 64 * DQ_S;
    int tid = threadIdx.x;
    int c = tid & 7, kb = tid >> 3;
#pragma unroll
    for (int r = 0; r < 8; r++) {
        int k = k0 + kb + r * 32;
        unsigned q = (unsigned)qw[(size_t)k * 4096 + c0 + c];
        unsigned z = (unsigned)qz[(size_t)(k >> 7) * 4096 + c0 + c];
        const float* srow = sc + (size_t)(k >> 7) * 32768 + (size_t)(c0 + c) * 8;
#pragma unroll
        for (int j = 0; j < 8; j++) {
            int sh = ((j >> 1) << 2) + ((j & 1) << 4);
            float v = ((float)((q >> sh) & 15u) - (float)((z >> sh) & 15u)) * srow[j];
            __nv_bfloat16 h, l; bf16_split(v, h, l);
            int n = c * 8 + j;
            shh[n * DQ_S + (k - k0)] = h;
            shl[n * DQ_S + (k - k0)] = l;
        }
    }
    __syncthreads();
    int n = tid >> 2, qd = tid & 3;
    size_t dst = (size_t)(c0 * 8 + n) * 1024 + k0 + qd * 64;
    const uint2* s2h = (const uint2*)(shh + n * DQ_S + qd * 64);
    const uint2* s2l = (const uint2*)(shl + n * DQ_S + qd * 64);
    uint2* dh = (uint2*)(g_W1h + dst);
    uint2* dl = (uint2*)(g_W1l + dst);
#pragma unroll
    for (int u = 0; u < 16; u++) { dh[u] = s2h[u]; dl[u] = s2l[u]; }
}

__global__ __launch_bounds__(256) void dequant2_t(
    const int* __restrict__ qw, const int* __restrict__ qz, const float* __restrict__ sc) {
    int c0 = blockIdx.x * 8;       // word columns (of 8192)
    int k0 = blockIdx.y * 256;     // k tile (of 512)
    extern __shared__ char smraw[];
    __nv_bfloat16* shh = (__nv_bfloat16*)smraw;
    __nv_bfloat16* shl = shh + 64 * DQ_S;
    int tid = threadIdx.x;
    int c = tid & 7, kb = tid >> 3;
#pragma unroll
    for (int r = 0; r < 8; r++) {
        int k = k0 + kb + r * 32;
        unsigned q = (unsigned)qw[(size_t)k * 8192 + c0 + c];
        unsigned z = (unsigned)qz[(size_t)(k >> 7) * 8192 + c0 + c];
        const float* srow = sc + (size_t)(k >> 7) * 65536 + (size_t)(c0 + c) * 8;
#pragma unroll
        for (int j = 0; j < 8; j++) {
            int sh = ((j >> 1) << 2) + ((j & 1) << 4);
            float v = ((float)((q >> sh) & 15u) - (float)((z >> sh) & 15u)) * srow[j];
            __nv_bfloat16 h, l; bf16_split(v, h, l);
            int n = c * 8 + j;
            shh[n * DQ_S + (k - k0)] = h;
            shl[n * DQ_S + (k - k0)] = l;
        }
    }
    __syncthreads();
    int n = tid >> 2, qd = tid & 3;
    size_t dst = (size_t)(c0 * 8 + n) * 512 + k0 + qd * 64;
    const uint2* s2h = (const uint2*)(shh + n * DQ_S + qd * 64);
    const uint2* s2l = (const uint2*)(shl + n * DQ_S + qd * 64);
    uint2* dh = (uint2*)(g_W2h + dst);
    uint2* dl = (uint2*)(g_W2l + dst);
#pragma unroll
    for (int u = 0; u < 16; u++) { dh[u] = s2h[u]; dl[u] = s2l[u]; }
}

// ================= x split ========================================================
__global__ __launch_bounds__(256) void xsplit_kernel(const float* __restrict__ x) {
    size_t i = ((size_t)blockIdx.x * 256 + threadIdx.x) * 4;
    float4 v = *(const float4*)(x + i);
    __nv_bfloat16 h0, l0, h1, l1, h2, l2, h3, l3;
    bf16_split(v.x, h0, l0); bf16_split(v.y, h1, l1);
    bf16_split(v.z, h2, l2); bf16_split(v.w, h3, l3);
    *(uint2*)(g_Xh + i) = make_uint2(pack2(h0, h1), pack2(h2, h3));
    *(uint2*)(g_Xl + i) = make_uint2(pack2(l0, l1), pack2(l2, l3));
}

__global__ void zero_kernel() {
    int i = threadIdx.x;
    if (i < NEXP) { g_cnt[i] = 0; g_pos[i] = 0; }
}

// ================= router ========================================================
__global__ __launch_bounds__(256) void router_kernel(
    const float* __restrict__ x, const float* __restrict__ gw) {
    int tbase = blockIdx.x * 4;
    __shared__ float4 xs4[4][256];
    __shared__ float part[4][64][4];
    __shared__ float logits[4][64];
    int tid = threadIdx.x;
    for (int i = tid; i < 1024; i += 256) {
        int tt = i >> 8;
        xs4[tt][i & 255] = ((const float4*)(x + (size_t)(tbase + tt) * HID))[i & 255];
    }
    __syncthreads();
    int e = tid >> 2, p = tid & 3;
    const float4* wr = (const float4*)(gw + (size_t)e * HID);
    float s0 = 0, s1 = 0, s2 = 0, s3 = 0;
    for (int k = 0; k < 64; k++) {
        int idx = k * 4 + p;
        float4 w = wr[idx];
        float4 a0 = xs4[0][idx]; s0 += a0.x * w.x + a0.y * w.y + a0.z * w.z + a0.w * w.w;
        float4 a1 = xs4[1][idx]; s1 += a1.x * w.x + a1.y * w.y + a1.z * w.z + a1.w * w.w;
        float4 a2 = xs4[2][idx]; s2 += a2.x * w.x + a2.y * w.y + a2.z * w.z + a2.w * w.w;
        float4 a3 = xs4[3][idx]; s3 += a3.x * w.x + a3.y * w.y + a3.z * w.z + a3.w * w.w;
    }
    part[0][e][p] = s0; part[1][e][p] = s1; part[2][e][p] = s2; part[3][e][p] = s3;
    __syncthreads();
    {
        int tt = tid >> 6, ee = tid & 63;
        logits[tt][ee] = part[tt][ee][0] + part[tt][ee][1] + part[tt][ee][2] + part[tt][ee][3];
    }
    __syncthreads();
    if (tid < 4) {
        int t = tbase + tid;
        unsigned long long used = 0ull;
        int idx[8]; float lv[8];
        for (int r = 0; r < 8; r++) {
            float best = -1e30f; int bi = 0;
            for (int i = 0; i < 64; i++) {
                if (!((used >> i) & 1ull) && logits[tid][i] > best) { best = logits[tid][i]; bi = i; }
            }
            used |= 1ull << bi; idx[r] = bi; lv[r] = best;
        }
        float m = lv[0], sum = 0.f, wk[8];
        for (int r = 0; r < 8; r++) { wk[r] = expf(lv[r] - m); sum += wk[r]; }
        float inv = 1.f / sum;
        for (int r = 0; r < 8; r++) {
            g_topk_idx[t * TOPK + r] = idx[r];
            g_topk_w[t * TOPK + r]   = wk[r] * inv;
            atomicAdd(&g_cnt[idx[r]], 1);
        }
    }
}

// ================= scan (+ tile worklist) + scatter ==============================
__global__ void scan_kernel() {
    int acc = 0;
    for (int i = 0; i < NEXP; i++) { g_base[i] = acc; acc += g_cnt[i]; }
    int tt = 0;
    for (int e = 0; e < NEXP; e++)
        for (int t = 0; t < g_cnt[e]; t += 128) { g_tile_e[tt] = e; g_tile_off[tt] = t; tt++; }
    g_ntiles = tt;
}

__global__ __launch_bounds__(256) void scatter_kernel() {
    int p = blockIdx.x * 256 + threadIdx.x;
    if (p >= T_TOK * TOPK) return;
    int e = g_topk_idx[p];
    int pos = g_base[e] + atomicAdd(&g_pos[e], 1);
    g_tok[pos] = p >> 3;
    g_tw[pos]  = g_topk_w[p];
    g_slot[p]  = pos;
}

// ================= ffn kernels (HMMA mma.sync, 3-term split bf16) ================
// block tile 128(M) x 128(N), KC=64; 8 warps as 2(M)x4(N) -> warp tile 64x32.
// smem: tok[128]@0, tw[128]@512, double buffers @1024: per buf {AH,AL,BH,BL} 16KB each.
#define FFN_SMEM (1024 + 2 * 65536)

__global__ __launch_bounds__(256, 1) void ffn1_kernel() {
    int tile = blockIdx.x;
    if (tile >= g_ntiles) return;
    int e = g_tile_e[tile];
    int tile0 = g_tile_off[tile];
    int ntile = blockIdx.y;
    int cnt = g_cnt[e];
    int nt = min(128, cnt - tile0);
    int base = g_base[e] + tile0;

    extern __shared__ char smraw[];
    int* tok_s = (int*)smraw;
    float* tw_s = (float*)(smraw + 512);
    uint32_t sb = smem_to_u32(smraw);
    int tid = threadIdx.x, lane = tid & 31, wid = tid >> 5;
    int wm = wid & 1, wn = wid >> 1;

    if (tid < 128) {
        if (tid < nt) { tok_s[tid] = g_tok[base + tid]; tw_s[tid] = g_tw[base + tid]; }
        else          { tok_s[tid] = g_tok[base];       tw_s[tid] = 0.f; }
    }
    __syncthreads();

    const __nv_bfloat16* WhE = g_W1h + ((size_t)e * 512 + (size_t)ntile * 128) * 1024;
    const __nv_bfloat16* WlE = g_W1l + ((size_t)e * 512 + (size_t)ntile * 128) * 1024;

    float acc[4][4][4];
#pragma unroll
    for (int a = 0; a < 4; a++)
#pragma unroll
        for (int b = 0; b < 4; b++)
#pragma unroll
            for (int u = 0; u < 4; u++) acc[a][b][u] = 0.f;

    auto load_chunk = [&](int c, int b) {
        int k0 = c * 64;
        uint32_t bufb = sb + 1024 + b * 65536;
        int c16 = tid & 7, row0 = tid >> 3;
#pragma unroll
        for (int it = 0; it < 4; it++) {
            int r = row0 + it * 32;
            uint32_t o = SW128((uint32_t)(r * 128 + c16 * 16));
            size_t asrc = (size_t)tok_s[r] * 1024 + k0 + c16 * 8;
            CP16(bufb + 0     + o, g_Xh + asrc);
            CP16(bufb + 16384 + o, g_Xl + asrc);
            size_t bsrc = (size_t)r * 1024 + k0 + c16 * 8;
            CP16(bufb + 32768 + o, WhE + bsrc);
            CP16(bufb + 49152 + o, WlE + bsrc);
        }
    };

    load_chunk(0, 0); CP_COMMIT();
    CP_WAIT0(); __syncthreads();

    for (int c = 0; c < 16; c++) {
        int b = c & 1;
        if (c + 1 < 16) { load_chunk(c + 1, (c + 1) & 1); CP_COMMIT(); }
        uint32_t bufb = sb + 1024 + b * 65536;
#pragma unroll
        for (int kk = 0; kk < 4; kk++) {
            uint32_t ah[4][4], al[4][4];
#pragma unroll
            for (int mf = 0; mf < 4; mf++) {
                int R = wm * 64 + mf * 16;
                ldsm4(ldsm_addr(bufb + 0,     R, kk, lane), ah[mf][0], ah[mf][1], ah[mf][2], ah[mf][3]);
                ldsm4(ldsm_addr(bufb + 16384, R, kk, lane), al[mf][0], al[mf][1], al[mf][2], al[mf][3]);
            }
#pragma unroll
            for (int nf2 = 0; nf2 < 2; nf2++) {
                int Rn = wn * 32 + nf2 * 16;
                uint32_t h0, h1, h2, h3, l0, l1, l2, l3;
                ldsm4(ldsm_addr(bufb + 32768, Rn, kk, lane), h0, h1, h2, h3);
                ldsm4(ldsm_addr(bufb + 49152, Rn, kk, lane), l0, l1, l2, l3);
#pragma unroll
                for (int mf = 0; mf < 4; mf++) {
                    float* cA = acc[mf][nf2 * 2];
                    float* cB = acc[mf][nf2 * 2 + 1];
                    mma16816(cA, ah[mf], h0, h2);
                    mma16816(cB, ah[mf], h1, h3);
                    mma16816(cA, ah[mf], l0, l2);
                    mma16816(cB, ah[mf], l1, l3);
                    mma16816(cA, al[mf], h0, h2);
                    mma16816(cB, al[mf], h1, h3);
                }
            }
        }
        if (c + 1 < 16) CP_WAIT0();
        __syncthreads();
    }

    // epilogue: silu * tw -> split bf16 -> H
#pragma unroll
    for (int mf = 0; mf < 4; mf++) {
#pragma unroll
        for (int half = 0; half < 2; half++) {
            int r = wm * 64 + mf * 16 + (lane >> 2) + half * 8;
            if (r < nt) {
                float tw = tw_s[r];
                int slot = base + r;
#pragma unroll
                for (int nf = 0; nf < 4; nf++) {
                    int ncol = ntile * 128 + wn * 32 + nf * 8 + (lane & 3) * 2;
                    float v0 = acc[mf][nf][half * 2 + 0];
                    float v1 = acc[mf][nf][half * 2 + 1];
                    v0 = v0 / (1.f + __expf(-v0)) * tw;
                    v1 = v1 / (1.f + __expf(-v1)) * tw;
                    __nv_bfloat16 h0, lo0, h1, lo1;
                    bf16_split(v0, h0, lo0); bf16_split(v1, h1, lo1);
                    *(uint32_t*)(g_Hh + (size_t)slot * 512 + ncol) = pack2(h0, h1);
                    *(uint32_t*)(g_Hl + (size_t)slot * 512 + ncol) = pack2(lo0, lo1);
                }
            }
        }
    }
}

__global__ __launch_bounds__(256, 1) void ffn2_kernel() {
    int tile = blockIdx.x;
    if (tile >= g_ntiles) return;
    int e = g_tile_e[tile];
    int tile0 = g_tile_off[tile];
    int ntile = blockIdx.y;
    int cnt = g_cnt[e];
    int nt = min(128, cnt - tile0);
    int base = g_base[e] + tile0;

    extern __shared__ char smraw[];
    uint32_t sb = smem_to_u32(smraw);
    int tid = threadIdx.x, lane = tid & 31, wid = tid >> 5;
    int wm = wid & 1, wn = wid >> 1;

    const __nv_bfloat16* WhE = g_W2h + ((size_t)e * 1024 + (size_t)ntile * 128) * 512;
    const __nv_bfloat16* WlE = g_W2l + ((size_t)e * 1024 + (size_t)ntile * 128) * 512;

    float acc[4][4][4];
#pragma unroll
    for (int a = 0; a < 4; a++)
#pragma unroll
        for (int b = 0; b < 4; b++)
#pragma unroll
            for (int u = 0; u < 4; u++) acc[a][b][u] = 0.f;

    auto load_chunk = [&](int c, int b) {
        int k0 = c * 64;
        uint32_t bufb = sb + 1024 + b * 65536;
        int c16 = tid & 7, row0 = tid >> 3;
#pragma unroll
        for (int it = 0; it < 4; it++) {
            int r = row0 + it * 32;
            int rc = min(r, nt - 1);
            uint32_t o = SW128((uint32_t)(r * 128 + c16 * 16));
            size_t asrc = (size_t)(base + rc) * 512 + k0 + c16 * 8;
            CP16(bufb + 0     + o, g_Hh + asrc);
            CP16(bufb + 16384 + o, g_Hl + asrc);
            size_t bsrc = (size_t)r * 512 + k0 + c16 * 8;
            CP16(bufb + 32768 + o, WhE + bsrc);
            CP16(bufb + 49152 + o, WlE + bsrc);
        }
    };

    load_chunk(0, 0); CP_COMMIT();
    CP_WAIT0(); __syncthreads();

    for (int c = 0; c < 8; c++) {
        int b = c & 1;
        if (c + 1 < 8) { load_chunk(c + 1, (c + 1) & 1); CP_COMMIT(); }
        uint32_t bufb = sb + 1024 + b * 65536;
#pragma unroll
        for (int kk = 0; kk < 4; kk++) {
            uint32_t ah[4][4], al[4][4];
#pragma unroll
            for (int mf = 0; mf < 4; mf++) {
                int R = wm * 64 + mf * 16;
                ldsm4(ldsm_addr(bufb + 0,     R, kk, lane), ah[mf][0], ah[mf][1], ah[mf][2], ah[mf][3]);
                ldsm4(ldsm_addr(bufb + 16384, R, kk, lane), al[mf][0], al[mf][1], al[mf][2], al[mf][3]);
            }
#pragma unroll
            for (int nf2 = 0; nf2 < 2; nf2++) {
                int Rn = wn * 32 + nf2 * 16;
                uint32_t h0, h1, h2, h3, l0, l1, l2, l3;
                ldsm4(ldsm_addr(bufb + 32768, Rn, kk, lane), h0, h1, h2, h3);
                ldsm4(ldsm_addr(bufb + 49152, Rn, kk, lane), l0, l1, l2, l3);
#pragma unroll
                for (int mf = 0; mf < 4; mf++) {
                    float* cA = acc[mf][nf2 * 2];
                    float* cB = acc[mf][nf2 * 2 + 1];
                    mma16816(cA, ah[mf], h0, h2);
                    mma16816(cB, ah[mf], h1, h3);
                    mma16816(cA, ah[mf], l0, l2);
                    mma16816(cB, ah[mf], l1, l3);
                    mma16816(cA, al[mf], h0, h2);
                    mma16816(cB, al[mf], h1, h3);
                }
            }
        }
        if (c + 1 < 8) CP_WAIT0();
        __syncthreads();
    }

    // epilogue: fp32 partials per slot
#pragma unroll
    for (int mf = 0; mf < 4; mf++) {
#pragma unroll
        for (int half = 0; half < 2; half++) {
            int r = wm * 64 + mf * 16 + (lane >> 2) + half * 8;
            if (r < nt) {
                int slot = base + r;
#pragma unroll
                for (int nf = 0; nf < 4; nf++) {
                    int ncol = ntile * 128 + wn * 32 + nf * 8 + (lane & 3) * 2;
                    *(float2*)(g_O2 + (size_t)slot * 1024 + ncol) =
                        make_float2(acc[mf][nf][half * 2], acc[mf][nf][half * 2 + 1]);
                }
            }
        }
    }
}

// ================= reduce: out[t] = sum_r O2[slot(t,r)] ==========================
__global__ __launch_bounds__(256) void reduce_kernel(float* __restrict__ out) {
    int t = blockIdx.x;
    __shared__ int sl[8];
    if (threadIdx.x < 8) sl[threadIdx.x] = g_slot[t * 8 + threadIdx.x];
    __syncthreads();
    int c = threadIdx.x * 4;
    float4 a = make_float4(0.f, 0.f, 0.f, 0.f);
#pragma unroll
    for (int r = 0; r < 8; r++) {
        float4 v = *(const float4*)(g_O2 + (size_t)sl[r] * 1024 + c);
        a.x += v.x; a.y += v.y; a.z += v.z; a.w += v.w;
    }
    *(float4*)(out + (size_t)t * 1024 + c) = a;
}

// ================= launch ========================================================
extern "C" void kernel_launch(void* const* d_in, const int* in_sizes, int n_in,
                              void* d_out, int out_size) {
    const float* x   = (const float*)d_in[0];
    const float* gw  = (const float*)d_in[1];
    const int*   qw1 = (const int*)d_in[2];
    const int*   qz1 = (const int*)d_in[3];
    const float* sc1 = (const float*)d_in[4];
    const int*   qw2 = (const int*)d_in[5];
    const int*   qz2 = (const int*)d_in[6];
    const float* sc2 = (const float*)d_in[7];
    float* out = (float*)d_out;

    const int DQ_SMEM = 2 * 64 * DQ_S * 2;
    cudaFuncSetAttribute(dequant1_t, cudaFuncAttributeMaxDynamicSharedMemorySize, DQ_SMEM);
    cudaFuncSetAttribute(dequant2_t, cudaFuncAttributeMaxDynamicSharedMemorySize, DQ_SMEM);
    cudaFuncSetAttribute(ffn1_kernel, cudaFuncAttributeMaxDynamicSharedMemorySize, FFN_SMEM);
    cudaFuncSetAttribute(ffn2_kernel, cudaFuncAttributeMaxDynamicSharedMemorySize, FFN_SMEM);

    dequant1_t<<<dim3(512, 4), 256, DQ_SMEM>>>(qw1, qz1, sc1);
    dequant2_t<<<dim3(1024, 2), 256, DQ_SMEM>>>(qw2, qz2, sc2);
    xsplit_kernel<<<2048, 256>>>(x);
    zero_kernel<<<1, 64>>>();
    router_kernel<<<T_TOK / 4, 256>>>(x, gw);
    scan_kernel<<<1, 1>>>();
    scatter_kernel<<<(T_TOK * TOPK + 255) / 256, 256>>>();
    ffn1_kernel<<<dim3(192, 4), 256, FFN_SMEM>>>();
    ffn2_kernel<<<dim3(192, 8), 256, FFN_SMEM>>>();
    reduce_kernel<<<T_TOK, 256>>>(out);
}

// round 6
// speedup vs baseline: 3.0849x; 1.9307x over previous
#include <cuda_runtime.h>
#include <cuda_fp16.h>
#include <math.h>
#include <stdint.h>

#define T_TOK 2048
#define HID   1024
#define NEXP  64
#define TOPK  8
#define ISZ   512
#define GRP   128

// ================= helpers ========================================================
__device__ __forceinline__ uint32_t smem_to_u32(const void* p) {
    uint32_t a;
    asm("{ .reg .u64 t; cvta.to.shared.u64 t, %1; cvt.u32.u64 %0, t; }" : "=r"(a) : "l"(p));
    return a;
}
#define SW128(o) ((o) ^ (((o) >> 3) & 0x70))

#define CP16(dst, src) \
    asm volatile("cp.async.cg.shared.global [%0], [%1], 16;" \
                 :: "r"((uint32_t)(dst)), "l"((const void*)(src)) : "memory")
#define CP_COMMIT() asm volatile("cp.async.commit_group;" ::: "memory")
#define CP_WAIT0()  asm volatile("cp.async.wait_group 0;" ::: "memory")

__device__ __forceinline__ void ldsm4(uint32_t addr, uint32_t& r0, uint32_t& r1,
                                      uint32_t& r2, uint32_t& r3) {
    asm volatile("ldmatrix.sync.aligned.m8n8.x4.shared.b16 {%0,%1,%2,%3}, [%4];"
                 : "=r"(r0), "=r"(r1), "=r"(r2), "=r"(r3) : "r"(addr));
}
__device__ __forceinline__ void mma16816(float* c, const uint32_t* a,
                                         uint32_t b0, uint32_t b1) {
    asm volatile("mma.sync.aligned.m16n8k16.row.col.f32.f16.f16.f32 "
                 "{%0,%1,%2,%3}, {%4,%5,%6,%7}, {%8,%9}, {%0,%1,%2,%3};"
                 : "+f"(c[0]), "+f"(c[1]), "+f"(c[2]), "+f"(c[3])
                 : "r"(a[0]), "r"(a[1]), "r"(a[2]), "r"(a[3]), "r"(b0), "r"(b1));
}
// ldsm address: tile rows of 64 fp16 (128 B), SW128-swizzled, base 1024-aligned.
__device__ __forceinline__ uint32_t ldsm_addr(uint32_t tile_base, int R, int kk, int lane) {
    int g = lane >> 3;
    int row = R + ((g & 1) << 3) + (lane & 7);
    uint32_t off = (uint32_t)(row * 128 + kk * 32 + ((g >> 1) << 4));
    return tile_base + SW128(off);
}
__device__ __forceinline__ uint32_t packh2(__half a, __half b) {
    return (uint32_t)__half_as_ushort(a) | ((uint32_t)__half_as_ushort(b) << 16);
}

// ================= device scratch =================================================
__device__ __half g_W1q[33554432];   // [E*I=32768][K=1024] exact (q-z), k-major
__device__ __half g_W2q[33554432];   // [E*H=65536][K=512]
__device__ __half g_Xq[2097152];     // [T=2048][1024]
__device__ __half g_Hq[8388608];     // [16384 slots][512]
__device__ float  g_O2[16777216];    // [16384 slots][1024]
__device__ int   g_topk_idx[T_TOK*TOPK];
__device__ float g_topk_w[T_TOK*TOPK];
__device__ int   g_cnt[NEXP];
__device__ int   g_base[NEXP];
__device__ int   g_pos[NEXP];
__device__ int   g_tok[T_TOK*TOPK];
__device__ float g_tw[T_TOK*TOPK];
__device__ int   g_slot[T_TOK*TOPK];
__device__ int   g_tile_e[256];
__device__ int   g_tile_off[256];
__device__ int   g_ntiles;

// ================= dequant: (q-z) exact -> fp16, transposed k-major ==============
// AWQ nibble j shift = (j>>1)*4 + (j&1)*16; dense column n = c*8+j -> output row n.
#define DQ_S 260
__global__ __launch_bounds__(256) void dequant1_t(
    const int* __restrict__ qw, const int* __restrict__ qz) {
    int c0 = blockIdx.x * 8;       // word columns (of 4096)
    int k0 = blockIdx.y * 256;     // k tile (of 1024)
    extern __shared__ char smraw[];
    __half* sh = (__half*)smraw;   // [64 n][260 k]
    int tid = threadIdx.x;
    int c = tid & 7, kb = tid >> 3;
#pragma unroll
    for (int r = 0; r < 8; r++) {
        int k = k0 + kb + r * 32;
        unsigned q = (unsigned)qw[(size_t)k * 4096 + c0 + c];
        unsigned z = (unsigned)qz[(size_t)(k >> 7) * 4096 + c0 + c];
#pragma unroll
        for (int j = 0; j < 8; j++) {
            int sh_b = ((j >> 1) << 2) + ((j & 1) << 4);
            int v = (int)((q >> sh_b) & 15u) - (int)((z >> sh_b) & 15u);
            sh[(c * 8 + j) * DQ_S + (k - k0)] = __int2half_rn(v);
        }
    }
    __syncthreads();
    int n = tid >> 2, qd = tid & 3;
    size_t dst = (size_t)(c0 * 8 + n) * 1024 + k0 + qd * 64;
    const uint2* s2 = (const uint2*)(sh + n * DQ_S + qd * 64);
    uint2* dp = (uint2*)(g_W1q + dst);
#pragma unroll
    for (int u = 0; u < 16; u++) dp[u] = s2[u];
}

__global__ __launch_bounds__(256) void dequant2_t(
    const int* __restrict__ qw, const int* __restrict__ qz) {
    int c0 = blockIdx.x * 8;       // word columns (of 8192)
    int k0 = blockIdx.y * 256;     // k tile (of 512)
    extern __shared__ char smraw[];
    __half* sh = (__half*)smraw;
    int tid = threadIdx.x;
    int c = tid & 7, kb = tid >> 3;
#pragma unroll
    for (int r = 0; r < 8; r++) {
        int k = k0 + kb + r * 32;
        unsigned q = (unsigned)qw[(size_t)k * 8192 + c0 + c];
        unsigned z = (unsigned)qz[(size_t)(k >> 7) * 8192 + c0 + c];
#pragma unroll
        for (int j = 0; j < 8; j++) {
            int sh_b = ((j >> 1) << 2) + ((j & 1) << 4);
            int v = (int)((q >> sh_b) & 15u) - (int)((z >> sh_b) & 15u);
            sh[(c * 8 + j) * DQ_S + (k - k0)] = __int2half_rn(v);
        }
    }
    __syncthreads();
    int n = tid >> 2, qd = tid & 3;
    size_t dst = (size_t)(c0 * 8 + n) * 512 + k0 + qd * 64;
    const uint2* s2 = (const uint2*)(sh + n * DQ_S + qd * 64);
    uint2* dp = (uint2*)(g_W2q + dst);
#pragma unroll
    for (int u = 0; u < 16; u++) dp[u] = s2[u];
}

// ================= x -> fp16 ======================================================
__global__ __launch_bounds__(256) void xcvt_kernel(const float* __restrict__ x) {
    size_t i = ((size_t)blockIdx.x * 256 + threadIdx.x) * 4;
    float4 v = *(const float4*)(x + i);
    *(uint2*)(g_Xq + i) = make_uint2(
        packh2(__float2half_rn(v.x), __float2half_rn(v.y)),
        packh2(__float2half_rn(v.z), __float2half_rn(v.w)));
}

__global__ void zero_kernel() {
    int i = threadIdx.x;
    if (i < NEXP) { g_cnt[i] = 0; g_pos[i] = 0; }
}

// ================= router ========================================================
__global__ __launch_bounds__(256) void router_kernel(
    const float* __restrict__ x, const float* __restrict__ gw) {
    int tbase = blockIdx.x * 4;
    __shared__ float4 xs4[4][256];
    __shared__ float part[4][64][4];
    __shared__ float logits[4][64];
    int tid = threadIdx.x;
    for (int i = tid; i < 1024; i += 256) {
        int tt = i >> 8;
        xs4[tt][i & 255] = ((const float4*)(x + (size_t)(tbase + tt) * HID))[i & 255];
    }
    __syncthreads();
    int e = tid >> 2, p = tid & 3;
    const float4* wr = (const float4*)(gw + (size_t)e * HID);
    float s0 = 0, s1 = 0, s2 = 0, s3 = 0;
    for (int k = 0; k < 64; k++) {
        int idx = k * 4 + p;
        float4 w = wr[idx];
        float4 a0 = xs4[0][idx]; s0 += a0.x * w.x + a0.y * w.y + a0.z * w.z + a0.w * w.w;
        float4 a1 = xs4[1][idx]; s1 += a1.x * w.x + a1.y * w.y + a1.z * w.z + a1.w * w.w;
        float4 a2 = xs4[2][idx]; s2 += a2.x * w.x + a2.y * w.y + a2.z * w.z + a2.w * w.w;
        float4 a3 = xs4[3][idx]; s3 += a3.x * w.x + a3.y * w.y + a3.z * w.z + a3.w * w.w;
    }
    part[0][e][p] = s0; part[1][e][p] = s1; part[2][e][p] = s2; part[3][e][p] = s3;
    __syncthreads();
    {
        int tt = tid >> 6, ee = tid & 63;
        logits[tt][ee] = part[tt][ee][0] + part[tt][ee][1] + part[tt][ee][2] + part[tt][ee][3];
    }
    __syncthreads();
    if (tid < 4) {
        int t = tbase + tid;
        unsigned long long used = 0ull;
        int idx[8]; float lv[8];
        for (int r = 0; r < 8; r++) {
            float best = -1e30f; int bi = 0;
            for (int i = 0; i < 64; i++) {
                if (!((used >> i) & 1ull) && logits[tid][i] > best) { best = logits[tid][i]; bi = i; }
            }
            used |= 1ull << bi; idx[r] = bi; lv[r] = best;
        }
        float m = lv[0], sum = 0.f, wk[8];
        for (int r = 0; r < 8; r++) { wk[r] = expf(lv[r] - m); sum += wk[r]; }
        float inv = 1.f / sum;
        for (int r = 0; r < 8; r++) {
            g_topk_idx[t * TOPK + r] = idx[r];
            g_topk_w[t * TOPK + r]   = wk[r] * inv;
            atomicAdd(&g_cnt[idx[r]], 1);
        }
    }
}

// ================= scan (+ tile worklist) + scatter ==============================
__global__ void scan_kernel() {
    int acc = 0;
    for (int i = 0; i < NEXP; i++) { g_base[i] = acc; acc += g_cnt[i]; }
    int tt = 0;
    for (int e = 0; e < NEXP; e++)
        for (int t = 0; t < g_cnt[e]; t += 128) { g_tile_e[tt] = e; g_tile_off[tt] = t; tt++; }
    g_ntiles = tt;
}

__global__ __launch_bounds__(256) void scatter_kernel() {
    int p = blockIdx.x * 256 + threadIdx.x;
    if (p >= T_TOK * TOPK) return;
    int e = g_topk_idx[p];
    int pos = g_base[e] + atomicAdd(&g_pos[e], 1);
    g_tok[pos] = p >> 3;
    g_tw[pos]  = g_topk_w[p];
    g_slot[p]  = pos;
}

// ================= ffn kernels (fp16 HMMA, exact int weights, group scales) ======
// block tile 128(M) x 128(N), KC=64; 8 warps as 2(M)x4(N) -> warp tile 64x32.
// Per 128-k group (2 chunks): accP += acc * s[g, col]; acc = 0.
// ffn1 smem: tok[128]@0, tw@512, sc[8][128]@1024(4KB), bufs @8192 (2 x {A16K,B16K}).
#define F1_SMEM (8192 + 2 * 32768)
#define F2_SMEM (4096 + 2 * 32768)

__global__ __launch_bounds__(256, 1) void ffn1_kernel(const float* __restrict__ sc1) {
    int tile = blockIdx.x;
    if (tile >= g_ntiles) return;
    int e = g_tile_e[tile];
    int tile0 = g_tile_off[tile];
    int ntile = blockIdx.y;
    int cnt = g_cnt[e];
    int nt = min(128, cnt - tile0);
    int base = g_base[e] + tile0;

    extern __shared__ char smraw[];
    int* tok_s = (int*)smraw;
    float* tw_s = (float*)(smraw + 512);
    float* sc_s = (float*)(smraw + 1024);   // [8][128]
    uint32_t sb = smem_to_u32(smraw);
    int tid = threadIdx.x, lane = tid & 31, wid = tid >> 5;
    int wm = wid & 1, wn = wid >> 1;

    if (tid < 128) {
        if (tid < nt) { tok_s[tid] = g_tok[base + tid]; tw_s[tid] = g_tw[base + tid]; }
        else          { tok_s[tid] = g_tok[base];       tw_s[tid] = 0.f; }
    }
#pragma unroll
    for (int i = tid; i < 1024; i += 256)
        sc_s[i] = sc1[(size_t)(i >> 7) * 32768 + e * 512 + ntile * 128 + (i & 127)];
    __syncthreads();

    const __half* WqE = g_W1q + ((size_t)e * 512 + (size_t)ntile * 128) * 1024;

    float acc[4][4][4], accP[4][4][4];
#pragma unroll
    for (int a = 0; a < 4; a++)
#pragma unroll
        for (int b = 0; b < 4; b++)
#pragma unroll
            for (int u = 0; u < 4; u++) { acc[a][b][u] = 0.f; accP[a][b][u] = 0.f; }

    auto load_chunk = [&](int c, int b) {
        int k0 = c * 64;
        uint32_t bufb = sb + 8192 + b * 32768;
        int c16 = tid & 7, row0 = tid >> 3;
#pragma unroll
        for (int it = 0; it < 4; it++) {
            int r = row0 + it * 32;
            uint32_t o = SW128((uint32_t)(r * 128 + c16 * 16));
            CP16(bufb + o,         g_Xq + (size_t)tok_s[r] * 1024 + k0 + c16 * 8);
            CP16(bufb + 16384 + o, WqE + (size_t)r * 1024 + k0 + c16 * 8);
        }
    };

    load_chunk(0, 0); CP_COMMIT();
    CP_WAIT0(); __syncthreads();

    for (int c = 0; c < 16; c++) {
        int b = c & 1;
        if (c + 1 < 16) { load_chunk(c + 1, (c + 1) & 1); CP_COMMIT(); }
        uint32_t bufb = sb + 8192 + b * 32768;
#pragma unroll
        for (int kk = 0; kk < 4; kk++) {
            uint32_t ah[4][4];
#pragma unroll
            for (int mf = 0; mf < 4; mf++)
                ldsm4(ldsm_addr(bufb, wm * 64 + mf * 16, kk, lane),
                      ah[mf][0], ah[mf][1], ah[mf][2], ah[mf][3]);
#pragma unroll
            for (int nf2 = 0; nf2 < 2; nf2++) {
                uint32_t b0, b1, b2, b3;
                ldsm4(ldsm_addr(bufb + 16384, wn * 32 + nf2 * 16, kk, lane), b0, b1, b2, b3);
#pragma unroll
                for (int mf = 0; mf < 4; mf++) {
                    mma16816(acc[mf][nf2 * 2],     ah[mf], b0, b2);
                    mma16816(acc[mf][nf2 * 2 + 1], ah[mf], b1, b3);
                }
            }
        }
        if (c & 1) {   // end of 128-k group: fold scale
            int g = c >> 1;
            const float* sg = sc_s + g * 128 + wn * 32 + (lane & 3) * 2;
#pragma unroll
            for (int nf = 0; nf < 4; nf++) {
                float s0 = sg[nf * 8], s1 = sg[nf * 8 + 1];
#pragma unroll
                for (int mf = 0; mf < 4; mf++) {
                    accP[mf][nf][0] += acc[mf][nf][0] * s0; acc[mf][nf][0] = 0.f;
                    accP[mf][nf][1] += acc[mf][nf][1] * s1; acc[mf][nf][1] = 0.f;
                    accP[mf][nf][2] += acc[mf][nf][2] * s0; acc[mf][nf][2] = 0.f;
                    accP[mf][nf][3] += acc[mf][nf][3] * s1; acc[mf][nf][3] = 0.f;
                }
            }
        }
        if (c + 1 < 16) CP_WAIT0();
        __syncthreads();
    }

    // epilogue: silu * tw -> fp16 H
#pragma unroll
    for (int mf = 0; mf < 4; mf++) {
#pragma unroll
        for (int half = 0; half < 2; half++) {
            int r = wm * 64 + mf * 16 + (lane >> 2) + half * 8;
            if (r < nt) {
                float tw = tw_s[r];
                int slot = base + r;
#pragma unroll
                for (int nf = 0; nf < 4; nf++) {
                    int ncol = ntile * 128 + wn * 32 + nf * 8 + (lane & 3) * 2;
                    float v0 = accP[mf][nf][half * 2 + 0];
                    float v1 = accP[mf][nf][half * 2 + 1];
                    v0 = v0 / (1.f + __expf(-v0)) * tw;
                    v1 = v1 / (1.f + __expf(-v1)) * tw;
                    *(uint32_t*)(g_Hq + (size_t)slot * 512 + ncol) =
                        packh2(__float2half_rn(v0), __float2half_rn(v1));
                }
            }
        }
    }
}

__global__ __launch_bounds__(256, 1) void ffn2_kernel(const float* __restrict__ sc2) {
    int tile = blockIdx.x;
    if (tile >= g_ntiles) return;
    int e = g_tile_e[tile];
    int tile0 = g_tile_off[tile];
    int ntile = blockIdx.y;
    int cnt = g_cnt[e];
    int nt = min(128, cnt - tile0);
    int base = g_base[e] + tile0;

    extern __shared__ char smraw[];
    float* sc_s = (float*)(smraw + 1024);   // [4][128]
    uint32_t sb = smem_to_u32(smraw);
    int tid = threadIdx.x, lane = tid & 31, wid = tid >> 5;
    int wm = wid & 1, wn = wid >> 1;

#pragma unroll
    for (int i = tid; i < 512; i += 256)
        sc_s[i] = sc2[(size_t)(i >> 7) * 65536 + e * 1024 + ntile * 128 + (i & 127)];
    __syncthreads();

    const __half* WqE = g_W2q + ((size_t)e * 1024 + (size_t)ntile * 128) * 512;

    float acc[4][4][4], accP[4][4][4];
#pragma unroll
    for (int a = 0; a < 4; a++)
#pragma unroll
        for (int b = 0; b < 4; b++)
#pragma unroll
            for (int u = 0; u < 4; u++) { acc[a][b][u] = 0.f; accP[a][b][u] = 0.f; }

    auto load_chunk = [&](int c, int b) {
        int k0 = c * 64;
        uint32_t bufb = sb + 4096 + b * 32768;
        int c16 = tid & 7, row0 = tid >> 3;
#pragma unroll
        for (int it = 0; it < 4; it++) {
            int r = row0 + it * 32;
            int rc = min(r, nt - 1);
            uint32_t o = SW128((uint32_t)(r * 128 + c16 * 16));
            CP16(bufb + o,         g_Hq + (size_t)(base + rc) * 512 + k0 + c16 * 8);
            CP16(bufb + 16384 + o, WqE + (size_t)r * 512 + k0 + c16 * 8);
        }
    };

    load_chunk(0, 0); CP_COMMIT();
    CP_WAIT0(); __syncthreads();

    for (int c = 0; c < 8; c++) {
        int b = c & 1;
        if (c + 1 < 8) { load_chunk(c + 1, (c + 1) & 1); CP_COMMIT(); }
        uint32_t bufb = sb + 4096 + b * 32768;
#pragma unroll
        for (int kk = 0; kk < 4; kk++) {
            uint32_t ah[4][4];
#pragma unroll
            for (int mf = 0; mf < 4; mf++)
                ldsm4(ldsm_addr(bufb, wm * 64 + mf * 16, kk, lane),
                      ah[mf][0], ah[mf][1], ah[mf][2], ah[mf][3]);
#pragma unroll
            for (int nf2 = 0; nf2 < 2; nf2++) {
                uint32_t b0, b1, b2, b3;
                ldsm4(ldsm_addr(bufb + 16384, wn * 32 + nf2 * 16, kk, lane), b0, b1, b2, b3);
#pragma unroll
                for (int mf = 0; mf < 4; mf++) {
                    mma16816(acc[mf][nf2 * 2],     ah[mf], b0, b2);
                    mma16816(acc[mf][nf2 * 2 + 1], ah[mf], b1, b3);
                }
            }
        }
        if (c & 1) {
            int g = c >> 1;
            const float* sg = sc_s + g * 128 + wn * 32 + (lane & 3) * 2;
#pragma unroll
            for (int nf = 0; nf < 4; nf++) {
                float s0 = sg[nf * 8], s1 = sg[nf * 8 + 1];
#pragma unroll
                for (int mf = 0; mf < 4; mf++) {
                    accP[mf][nf][0] += acc[mf][nf][0] * s0; acc[mf][nf][0] = 0.f;
                    accP[mf][nf][1] += acc[mf][nf][1] * s1; acc[mf][nf][1] = 0.f;
                    accP[mf][nf][2] += acc[mf][nf][2] * s0; acc[mf][nf][2] = 0.f;
                    accP[mf][nf][3] += acc[mf][nf][3] * s1; acc[mf][nf][3] = 0.f;
                }
            }
        }
        if (c + 1 < 8) CP_WAIT0();
        __syncthreads();
    }

    // epilogue: fp32 partials per slot
#pragma unroll
    for (int mf = 0; mf < 4; mf++) {
#pragma unroll
        for (int half = 0; half < 2; half++) {
            int r = wm * 64 + mf * 16 + (lane >> 2) + half * 8;
            if (r < nt) {
                int slot = base + r;
#pragma unroll
                for (int nf = 0; nf < 4; nf++) {
                    int ncol = ntile * 128 + wn * 32 + nf * 8 + (lane & 3) * 2;
                    *(float2*)(g_O2 + (size_t)slot * 1024 + ncol) =
                        make_float2(accP[mf][nf][half * 2], accP[mf][nf][half * 2 + 1]);
                }
            }
        }
    }
}

// ================= reduce: out[t] = sum_r O2[slot(t,r)] ==========================
__global__ __launch_bounds__(256) void reduce_kernel(float* __restrict__ out) {
    int t = blockIdx.x;
    __shared__ int sl[8];
    if (threadIdx.x < 8) sl[threadIdx.x] = g_slot[t * 8 + threadIdx.x];
    __syncthreads();
    int c = threadIdx.x * 4;
    float4 a = make_float4(0.f, 0.f, 0.f, 0.f);
#pragma unroll
    for (int r = 0; r < 8; r++) {
        float4 v = *(const float4*)(g_O2 + (size_t)sl[r] * 1024 + c);
        a.x += v.x; a.y += v.y; a.z += v.z; a.w += v.w;
    }
    *(float4*)(out + (size_t)t * 1024 + c) = a;
}

// ================= launch ========================================================
extern "C" void kernel_launch(void* const* d_in, const int* in_sizes, int n_in,
                              void* d_out, int out_size) {
    const float* x   = (const float*)d_in[0];
    const float* gw  = (const float*)d_in[1];
    const int*   qw1 = (const int*)d_in[2];
    const int*   qz1 = (const int*)d_in[3];
    const float* sc1 = (const float*)d_in[4];
    const int*   qw2 = (const int*)d_in[5];
    const int*   qz2 = (const int*)d_in[6];
    const float* sc2 = (const float*)d_in[7];
    float* out = (float*)d_out;

    const int DQ_SMEM = 64 * DQ_S * 2;
    cudaFuncSetAttribute(dequant1_t, cudaFuncAttributeMaxDynamicSharedMemorySize, DQ_SMEM);
    cudaFuncSetAttribute(dequant2_t, cudaFuncAttributeMaxDynamicSharedMemorySize, DQ_SMEM);
    cudaFuncSetAttribute(ffn1_kernel, cudaFuncAttributeMaxDynamicSharedMemorySize, F1_SMEM);
    cudaFuncSetAttribute(ffn2_kernel, cudaFuncAttributeMaxDynamicSharedMemorySize, F2_SMEM);

    dequant1_t<<<dim3(512, 4), 256, DQ_SMEM>>>(qw1, qz1);
    dequant2_t<<<dim3(1024, 2), 256, DQ_SMEM>>>(qw2, qz2);
    xcvt_kernel<<<2048, 256>>>(x);
    zero_kernel<<<1, 64>>>();
    router_kernel<<<T_TOK / 4, 256>>>(x, gw);
    scan_kernel<<<1, 1>>>();
    scatter_kernel<<<(T_TOK * TOPK + 255) / 256, 256>>>();
    ffn1_kernel<<<dim3(192, 4), 256, F1_SMEM>>>(sc1);
    ffn2_kernel<<<dim3(192, 8), 256, F2_SMEM>>>(sc2);
    reduce_kernel<<<T_TOK, 256>>>(out);
}

// round 10
// speedup vs baseline: 3.5813x; 1.1609x over previous
#include <cuda_runtime.h>
#include <cuda_fp16.h>
#include <math.h>
#include <stdint.h>

#define T_TOK 2048
#define HID   1024
#define NEXP  64
#define TOPK  8
#define ISZ   512
#define GRP   128

// ================= helpers ========================================================
__device__ __forceinline__ uint32_t smem_to_u32(const void* p) {
    uint32_t a;
    asm("{ .reg .u64 t; cvta.to.shared.u64 t, %1; cvt.u32.u64 %0, t; }" : "=r"(a) : "l"(p));
    return a;
}
#define SW128(o) ((o) ^ (((o) >> 3) & 0x70))

#define CP16(dst, src) \
    asm volatile("cp.async.cg.shared.global [%0], [%1], 16;" \
                 :: "r"((uint32_t)(dst)), "l"((const void*)(src)) : "memory")
#define CP_COMMIT() asm volatile("cp.async.commit_group;" ::: "memory")
#define CP_WAIT0()  asm volatile("cp.async.wait_group 0;" ::: "memory")

__device__ __forceinline__ void ldsm4(uint32_t addr, uint32_t& r0, uint32_t& r1,
                                      uint32_t& r2, uint32_t& r3) {
    asm volatile("ldmatrix.sync.aligned.m8n8.x4.shared.b16 {%0,%1,%2,%3}, [%4];"
                 : "=r"(r0), "=r"(r1), "=r"(r2), "=r"(r3) : "r"(addr));
}
__device__ __forceinline__ void mma16816(float* c, const uint32_t* a,
                                         uint32_t b0, uint32_t b1) {
    asm volatile("mma.sync.aligned.m16n8k16.row.col.f32.f16.f16.f32 "
                 "{%0,%1,%2,%3}, {%4,%5,%6,%7}, {%8,%9}, {%0,%1,%2,%3};"
                 : "+f"(c[0]), "+f"(c[1]), "+f"(c[2]), "+f"(c[3])
                 : "r"(a[0]), "r"(a[1]), "r"(a[2]), "r"(a[3]), "r"(b0), "r"(b1));
}
// ldsm address: tile rows of 64 fp16 (128 B), SW128-swizzled, base 1024-aligned.
__device__ __forceinline__ uint32_t ldsm_addr(uint32_t tile_base, int R, int kk, int lane) {
    int g = lane >> 3;
    int row = R + ((g & 1) << 3) + (lane & 7);
    uint32_t off = (uint32_t)(row * 128 + kk * 32 + ((g >> 1) << 4));
    return tile_base + SW128(off);
}
__device__ __forceinline__ uint32_t packh2(__half a, __half b) {
    return (uint32_t)__half_as_ushort(a) | ((uint32_t)__half_as_ushort(b) << 16);
}

// ================= device scratch =================================================
__device__ __half g_W1q[33554432];   // [E*I=32768][K=1024] pre-scaled fp16, k-major
__device__ __half g_W2q[33554432];   // [E*H=65536][K=512]
__device__ __half g_Xq[2097152];     // [T=2048][1024]
__device__ __half g_Hq[8388608];     // [16384 slots][512]
__device__ float  g_O2[16777216];    // [16384 slots][1024]
__device__ int   g_topk_idx[T_TOK*TOPK];
__device__ float g_topk_w[T_TOK*TOPK];
__device__ int   g_cnt[NEXP];
__device__ int   g_base[NEXP];
__device__ int   g_pos[NEXP];
__device__ int   g_tok[T_TOK*TOPK];
__device__ float g_tw[T_TOK*TOPK];
__device__ int   g_slot[T_TOK*TOPK];
__device__ int   g_tile_e[256];
__device__ int   g_tile_off[256];
__device__ int   g_ntiles;

// ================= dequant: (q-z)*s -> fp16, transposed k-major ==================
// AWQ nibble j shift = (j>>1)*4 + (j&1)*16; dense column n = c*8+j -> output row n.
#define DQ_S 260
__global__ __launch_bounds__(256) void dequant1_t(
    const int* __restrict__ qw, const int* __restrict__ qz, const float* __restrict__ sc) {
    int c0 = blockIdx.x * 8;       // word columns (of 4096)
    int k0 = blockIdx.y * 256;     // k tile (of 1024)
    extern __shared__ char smraw[];
    __half* sh = (__half*)smraw;   // [64 n][260 k]
    int tid = threadIdx.x;
    int c = tid & 7, kb = tid >> 3;
#pragma unroll
    for (int r = 0; r < 8; r++) {
        int k = k0 + kb + r * 32;
        unsigned q = (unsigned)qw[(size_t)k * 4096 + c0 + c];
        unsigned z = (unsigned)qz[(size_t)(k >> 7) * 4096 + c0 + c];
        const float* srow = sc + (size_t)(k >> 7) * 32768 + (size_t)(c0 + c) * 8;
#pragma unroll
        for (int j = 0; j < 8; j++) {
            int sh_b = ((j >> 1) << 2) + ((j & 1) << 4);
            float v = (float)((int)((q >> sh_b) & 15u) - (int)((z >> sh_b) & 15u)) * srow[j];
            sh[(c * 8 + j) * DQ_S + (k - k0)] = __float2half_rn(v);
        }
    }
    __syncthreads();
    int n = tid >> 2, qd = tid & 3;
    size_t dst = (size_t)(c0 * 8 + n) * 1024 + k0 + qd * 64;
    const uint2* s2 = (const uint2*)(sh + n * DQ_S + qd * 64);
    uint2* dp = (uint2*)(g_W1q + dst);
#pragma unroll
    for (int u = 0; u < 16; u++) dp[u] = s2[u];
}

__global__ __launch_bounds__(256) void dequant2_t(
    const int* __restrict__ qw, const int* __restrict__ qz, const float* __restrict__ sc) {
    int c0 = blockIdx.x * 8;       // word columns (of 8192)
    int k0 = blockIdx.y * 256;     // k tile (of 512)
    extern __shared__ char smraw[];
    __half* sh = (__half*)smraw;
    int tid = threadIdx.x;
    int c = tid & 7, kb = tid >> 3;
#pragma unroll
    for (int r = 0; r < 8; r++) {
        int k = k0 + kb + r * 32;
        unsigned q = (unsigned)qw[(size_t)k * 8192 + c0 + c];
        unsigned z = (unsigned)qz[(size_t)(k >> 7) * 8192 + c0 + c];
        const float* srow = sc + (size_t)(k >> 7) * 65536 + (size_t)(c0 + c) * 8;
#pragma unroll
        for (int j = 0; j < 8; j++) {
            int sh_b = ((j >> 1) << 2) + ((j & 1) << 4);
            float v = (float)((int)((q >> sh_b) & 15u) - (int)((z >> sh_b) & 15u)) * srow[j];
            sh[(c * 8 + j) * DQ_S + (k - k0)] = __float2half_rn(v);
        }
    }
    __syncthreads();
    int n = tid >> 2, qd = tid & 3;
    size_t dst = (size_t)(c0 * 8 + n) * 512 + k0 + qd * 64;
    const uint2* s2 = (const uint2*)(sh + n * DQ_S + qd * 64);
    uint2* dp = (uint2*)(g_W2q + dst);
#pragma unroll
    for (int u = 0; u < 16; u++) dp[u] = s2[u];
}

// ================= x -> fp16 ======================================================
__global__ __launch_bounds__(256) void xcvt_kernel(const float* __restrict__ x) {
    size_t i = ((size_t)blockIdx.x * 256 + threadIdx.x) * 4;
    float4 v = *(const float4*)(x + i);
    *(uint2*)(g_Xq + i) = make_uint2(
        packh2(__float2half_rn(v.x), __float2half_rn(v.y)),
        packh2(__float2half_rn(v.z), __float2half_rn(v.w)));
}

__global__ void zero_kernel() {
    int i = threadIdx.x;
    if (i < NEXP) { g_cnt[i] = 0; g_pos[i] = 0; }
}

// ================= router ========================================================
__global__ __launch_bounds__(256) void router_kernel(
    const float* __restrict__ x, const float* __restrict__ gw) {
    int tbase = blockIdx.x * 4;
    __shared__ float4 xs4[4][256];
    __shared__ float part[4][64][4];
    __shared__ float logits[4][64];
    int tid = threadIdx.x;
    for (int i = tid; i < 1024; i += 256) {
        int tt = i >> 8;
        xs4[tt][i & 255] = ((const float4*)(x + (size_t)(tbase + tt) * HID))[i & 255];
    }
    __syncthreads();
    int e = tid >> 2, p = tid & 3;
    const float4* wr = (const float4*)(gw + (size_t)e * HID);
    float s0 = 0, s1 = 0, s2 = 0, s3 = 0;
    for (int k = 0; k < 64; k++) {
        int idx = k * 4 + p;
        float4 w = wr[idx];
        float4 a0 = xs4[0][idx]; s0 += a0.x * w.x + a0.y * w.y + a0.z * w.z + a0.w * w.w;
        float4 a1 = xs4[1][idx]; s1 += a1.x * w.x + a1.y * w.y + a1.z * w.z + a1.w * w.w;
        float4 a2 = xs4[2][idx]; s2 += a2.x * w.x + a2.y * w.y + a2.z * w.z + a2.w * w.w;
        float4 a3 = xs4[3][idx]; s3 += a3.x * w.x + a3.y * w.y + a3.z * w.z + a3.w * w.w;
    }
    part[0][e][p] = s0; part[1][e][p] = s1; part[2][e][p] = s2; part[3][e][p] = s3;
    __syncthreads();
    {
        int tt = tid >> 6, ee = tid & 63;
        logits[tt][ee] = part[tt][ee][0] + part[tt][ee][1] + part[tt][ee][2] + part[tt][ee][3];
    }
    __syncthreads();
    if (tid < 4) {
        int t = tbase + tid;
        unsigned long long used = 0ull;
        int idx[8]; float lv[8];
        for (int r = 0; r < 8; r++) {
            float best = -1e30f; int bi = 0;
            for (int i = 0; i < 64; i++) {
                if (!((used >> i) & 1ull) && logits[tid][i] > best) { best = logits[tid][i]; bi = i; }
            }
            used |= 1ull << bi; idx[r] = bi; lv[r] = best;
        }
        float m = lv[0], sum = 0.f, wk[8];
        for (int r = 0; r < 8; r++) { wk[r] = expf(lv[r] - m); sum += wk[r]; }
        float inv = 1.f / sum;
        for (int r = 0; r < 8; r++) {
            g_topk_idx[t * TOPK + r] = idx[r];
            g_topk_w[t * TOPK + r]   = wk[r] * inv;
            atomicAdd(&g_cnt[idx[r]], 1);
        }
    }
}

// ================= scan (+ tile worklist) + scatter ==============================
__global__ void scan_kernel() {
    int acc = 0;
    for (int i = 0; i < NEXP; i++) { g_base[i] = acc; acc += g_cnt[i]; }
    int tt = 0;
    for (int e = 0; e < NEXP; e++)
        for (int t = 0; t < g_cnt[e]; t += 128) { g_tile_e[tt] = e; g_tile_off[tt] = t; tt++; }
    g_ntiles = tt;
}

__global__ __launch_bounds__(256) void scatter_kernel() {
    int p = blockIdx.x * 256 + threadIdx.x;
    if (p >= T_TOK * TOPK) return;
    int e = g_topk_idx[p];
    int pos = g_base[e] + atomicAdd(&g_pos[e], 1);
    g_tok[pos] = p >> 3;
    g_tw[pos]  = g_topk_w[p];
    g_slot[p]  = pos;
}

// ================= ffn kernels (fp16 HMMA, pre-scaled weights) ===================
// block tile 128(M) x 128(N), KC=64; 8 warps as 2(M)x4(N) -> warp tile 64x32.
// smem: tok[128]@0, tw[128]@512, double buffers @1024: {A 16KB, B 16KB} x 2.
// 66.5 KB smem + <=128 regs -> 2 CTAs/SM for cross-CTA latency hiding.
#define F1_SMEM (1024 + 2 * 32768)
#define F2_SMEM (1024 + 2 * 32768)

__global__ __launch_bounds__(256, 2) void ffn1_kernel() {
    int tile = blockIdx.x;
    if (tile >= g_ntiles) return;
    int e = g_tile_e[tile];
    int tile0 = g_tile_off[tile];
    int ntile = blockIdx.y;
    int cnt = g_cnt[e];
    int nt = min(128, cnt - tile0);
    int base = g_base[e] + tile0;

    extern __shared__ char smraw[];
    int* tok_s = (int*)smraw;
    float* tw_s = (float*)(smraw + 512);
    uint32_t sb = smem_to_u32(smraw);
    int tid = threadIdx.x, lane = tid & 31, wid = tid >> 5;
    int wm = wid & 1, wn = wid >> 1;

    if (tid < 128) {
        if (tid < nt) { tok_s[tid] = g_tok[base + tid]; tw_s[tid] = g_tw[base + tid]; }
        else          { tok_s[tid] = g_tok[base];       tw_s[tid] = 0.f; }
    }
    __syncthreads();

    const __half* WqE = g_W1q + ((size_t)e * 512 + (size_t)ntile * 128) * 1024;

    float acc[4][4][4];
#pragma unroll
    for (int a = 0; a < 4; a++)
#pragma unroll
        for (int b = 0; b < 4; b++)
#pragma unroll
            for (int u = 0; u < 4; u++) acc[a][b][u] = 0.f;

    auto load_chunk = [&](int c, int b) {
        int k0 = c * 64;
        uint32_t bufb = sb + 1024 + b * 32768;
        int c16 = tid & 7, row0 = tid >> 3;
#pragma unroll
        for (int it = 0; it < 4; it++) {
            int r = row0 + it * 32;
            uint32_t o = SW128((uint32_t)(r * 128 + c16 * 16));
            CP16(bufb + o,         g_Xq + (size_t)tok_s[r] * 1024 + k0 + c16 * 8);
            CP16(bufb + 16384 + o, WqE + (size_t)r * 1024 + k0 + c16 * 8);
        }
    };

    load_chunk(0, 0); CP_COMMIT();
    CP_WAIT0(); __syncthreads();

    for (int c = 0; c < 16; c++) {
        int b = c & 1;
        if (c + 1 < 16) { load_chunk(c + 1, (c + 1) & 1); CP_COMMIT(); }
        uint32_t bufb = sb + 1024 + b * 32768;
#pragma unroll
        for (int kk = 0; kk < 4; kk++) {
            uint32_t ah[4][4];
#pragma unroll
            for (int mf = 0; mf < 4; mf++)
                ldsm4(ldsm_addr(bufb, wm * 64 + mf * 16, kk, lane),
                      ah[mf][0], ah[mf][1], ah[mf][2], ah[mf][3]);
#pragma unroll
            for (int nf2 = 0; nf2 < 2; nf2++) {
                uint32_t b0, b1, b2, b3;
                ldsm4(ldsm_addr(bufb + 16384, wn * 32 + nf2 * 16, kk, lane), b0, b1, b2, b3);
#pragma unroll
                for (int mf = 0; mf < 4; mf++) {
                    mma16816(acc[mf][nf2 * 2],     ah[mf], b0, b2);
                    mma16816(acc[mf][nf2 * 2 + 1], ah[mf], b1, b3);
                }
            }
        }
        if (c + 1 < 16) CP_WAIT0();
        __syncthreads();
    }

    // epilogue: silu * tw -> fp16 H
#pragma unroll
    for (int mf = 0; mf < 4; mf++) {
#pragma unroll
        for (int half = 0; half < 2; half++) {
            int r = wm * 64 + mf * 16 + (lane >> 2) + half * 8;
            if (r < nt) {
                float tw = tw_s[r];
                int slot = base + r;
#pragma unroll
                for (int nf = 0; nf < 4; nf++) {
                    int ncol = ntile * 128 + wn * 32 + nf * 8 + (lane & 3) * 2;
                    float v0 = acc[mf][nf][half * 2 + 0];
                    float v1 = acc[mf][nf][half * 2 + 1];
                    v0 = v0 / (1.f + __expf(-v0)) * tw;
                    v1 = v1 / (1.f + __expf(-v1)) * tw;
                    *(uint32_t*)(g_Hq + (size_t)slot * 512 + ncol) =
                        packh2(__float2half_rn(v0), __float2half_rn(v1));
                }
            }
        }
    }
}

__global__ __launch_bounds__(256, 2) void ffn2_kernel() {
    int tile = blockIdx.x;
    if (tile >= g_ntiles) return;
    int e = g_tile_e[tile];
    int tile0 = g_tile_off[tile];
    int ntile = blockIdx.y;
    int cnt = g_cnt[e];
    int nt = min(128, cnt - tile0);
    int base = g_base[e] + tile0;

    extern __shared__ char smraw[];
    uint32_t sb = smem_to_u32(smraw);
    int tid = threadIdx.x, lane = tid & 31, wid = tid >> 5;
    int wm = wid & 1, wn = wid >> 1;

    const __half* WqE = g_W2q + ((size_t)e * 1024 + (size_t)ntile * 128) * 512;

    float acc[4][4][4];
#pragma unroll
    for (int a = 0; a < 4; a++)
#pragma unroll
        for (int b = 0; b < 4; b++)
#pragma unroll
            for (int u = 0; u < 4; u++) acc[a][b][u] = 0.f;

    auto load_chunk = [&](int c, int b) {
        int k0 = c * 64;
        uint32_t bufb = sb + 1024 + b * 32768;
        int c16 = tid & 7, row0 = tid >> 3;
#pragma unroll
        for (int it = 0; it < 4; it++) {
            int r = row0 + it * 32;
            int rc = min(r, nt - 1);
            uint32_t o = SW128((uint32_t)(r * 128 + c16 * 16));
            CP16(bufb + o,         g_Hq + (size_t)(base + rc) * 512 + k0 + c16 * 8);
            CP16(bufb + 16384 + o, WqE + (size_t)r * 512 + k0 + c16 * 8);
        }
    };

    load_chunk(0, 0); CP_COMMIT();
    CP_WAIT0(); __syncthreads();

    for (int c = 0; c < 8; c++) {
        int b = c & 1;
        if (c + 1 < 8) { load_chunk(c + 1, (c + 1) & 1); CP_COMMIT(); }
        uint32_t bufb = sb + 1024 + b * 32768;
#pragma unroll
        for (int kk = 0; kk < 4; kk++) {
            uint32_t ah[4][4];
#pragma unroll
            for (int mf = 0; mf < 4; mf++)
                ldsm4(ldsm_addr(bufb, wm * 64 + mf * 16, kk, lane),
                      ah[mf][0], ah[mf][1], ah[mf][2], ah[mf][3]);
#pragma unroll
            for (int nf2 = 0; nf2 < 2; nf2++) {
                uint32_t b0, b1, b2, b3;
                ldsm4(ldsm_addr(bufb + 16384, wn * 32 + nf2 * 16, kk, lane), b0, b1, b2, b3);
#pragma unroll
                for (int mf = 0; mf < 4; mf++) {
                    mma16816(acc[mf][nf2 * 2],     ah[mf], b0, b2);
                    mma16816(acc[mf][nf2 * 2 + 1], ah[mf], b1, b3);
                }
            }
        }
        if (c + 1 < 8) CP_WAIT0();
        __syncthreads();
    }

    // epilogue: fp32 partials per slot
#pragma unroll
    for (int mf = 0; mf < 4; mf++) {
#pragma unroll
        for (int half = 0; half < 2; half++) {
            int r = wm * 64 + mf * 16 + (lane >> 2) + half * 8;
            if (r < nt) {
                int slot = base + r;
#pragma unroll
                for (int nf = 0; nf < 4; nf++) {
                    int ncol = ntile * 128 + wn * 32 + nf * 8 + (lane & 3) * 2;
                    *(float2*)(g_O2 + (size_t)slot * 1024 + ncol) =
                        make_float2(acc[mf][nf][half * 2], acc[mf][nf][half * 2 + 1]);
                }
            }
        }
    }
}

// ================= reduce: out[t] = sum_r O2[slot(t,r)] ==========================
__global__ __launch_bounds__(256) void reduce_kernel(float* __restrict__ out) {
    int t = blockIdx.x;
    __shared__ int sl[8];
    if (threadIdx.x < 8) sl[threadIdx.x] = g_slot[t * 8 + threadIdx.x];
    __syncthreads();
    int c = threadIdx.x * 4;
    float4 a = make_float4(0.f, 0.f, 0.f, 0.f);
#pragma unroll
    for (int r = 0; r < 8; r++) {
        float4 v = *(const float4*)(g_O2 + (size_t)sl[r] * 1024 + c);
        a.x += v.x; a.y += v.y; a.z += v.z; a.w += v.w;
    }
    *(float4*)(out + (size_t)t * 1024 + c) = a;
}

// ================= launch ========================================================
extern "C" void kernel_launch(void* const* d_in, const int* in_sizes, int n_in,
                              void* d_out, int out_size) {
    const float* x   = (const float*)d_in[0];
    const float* gw  = (const float*)d_in[1];
    const int*   qw1 = (const int*)d_in[2];
    const int*   qz1 = (const int*)d_in[3];
    const float* sc1 = (const float*)d_in[4];
    const int*   qw2 = (const int*)d_in[5];
    const int*   qz2 = (const int*)d_in[6];
    const float* sc2 = (const float*)d_in[7];
    float* out = (float*)d_out;

    const int DQ_SMEM = 64 * DQ_S * 2;
    cudaFuncSetAttribute(dequant1_t, cudaFuncAttributeMaxDynamicSharedMemorySize, DQ_SMEM);
    cudaFuncSetAttribute(dequant2_t, cudaFuncAttributeMaxDynamicSharedMemorySize, DQ_SMEM);
    cudaFuncSetAttribute(ffn1_kernel, cudaFuncAttributeMaxDynamicSharedMemorySize, F1_SMEM);
    cudaFuncSetAttribute(ffn2_kernel, cudaFuncAttributeMaxDynamicSharedMemorySize, F2_SMEM);

    dequant1_t<<<dim3(512, 4), 256, DQ_SMEM>>>(qw1, qz1, sc1);
    dequant2_t<<<dim3(1024, 2), 256, DQ_SMEM>>>(qw2, qz2, sc2);
    xcvt_kernel<<<2048, 256>>>(x);
    zero_kernel<<<1, 64>>>();
    router_kernel<<<T_TOK / 4, 256>>>(x, gw);
    scan_kernel<<<1, 1>>>();
    scatter_kernel<<<(T_TOK * TOPK + 255) / 256, 256>>>();
    ffn1_kernel<<<dim3(192, 4), 256, F1_SMEM>>>();
    ffn2_kernel<<<dim3(192, 8), 256, F2_SMEM>>>();
    reduce_kernel<<<T_TOK, 256>>>(out);
}